// round 6
// baseline (speedup 1.0000x reference)
#include <cuda_runtime.h>
#include <cuda_bf16.h>
#include <cstdint>

#define NN 8192
#define FD 10
#define HD 64
#define EMX 524288

__device__ float g_h[2][NN * HD];
__device__ __nv_bfloat16 g_hi[NN * HD];
__device__ __nv_bfloat16 g_lo[NN * HD];
__device__ int g_cnt[NN];
__device__ int g_start[NN];
__device__ int g_fill[NN];
__device__ int g_csr[EMX];

// ---------------------------------------------------------------------------
// helpers
// ---------------------------------------------------------------------------
__device__ __forceinline__ uint32_t smem_u32(const void* p) {
    uint32_t a;
    asm("{ .reg .u64 t; cvta.to.shared.u64 t, %1; cvt.u32.u64 %0, t; }"
        : "=r"(a) : "l"(p));
    return a;
}

__device__ __forceinline__ void ldm_x4(uint32_t* r, uint32_t addr) {
    asm volatile("ldmatrix.sync.aligned.m8n8.x4.shared.b16 {%0,%1,%2,%3}, [%4];"
                 : "=r"(r[0]), "=r"(r[1]), "=r"(r[2]), "=r"(r[3]) : "r"(addr));
}
__device__ __forceinline__ void ldm_x2(uint32_t* r, uint32_t addr) {
    asm volatile("ldmatrix.sync.aligned.m8n8.x2.shared.b16 {%0,%1}, [%2];"
                 : "=r"(r[0]), "=r"(r[1]) : "r"(addr));
}
__device__ __forceinline__ void mma_bf16(float* c, const uint32_t* a,
                                         const uint32_t* b) {
    asm volatile(
        "mma.sync.aligned.m16n8k16.row.col.f32.bf16.bf16.f32 "
        "{%0,%1,%2,%3}, {%4,%5,%6,%7}, {%8,%9}, {%0,%1,%2,%3};"
        : "+f"(c[0]), "+f"(c[1]), "+f"(c[2]), "+f"(c[3])
        : "r"(a[0]), "r"(a[1]), "r"(a[2]), "r"(a[3]), "r"(b[0]), "r"(b[1]));
}

#define SWZ(bo) ((bo) ^ (((bo) >> 3) & 0x70))

// ---------------------------------------------------------------------------
// h0 = relu(features @ W_node + b_node)
// ---------------------------------------------------------------------------
__global__ void k_node(const float* __restrict__ feat,
                       const float* __restrict__ Wn,
                       const float* __restrict__ bn) {
    int row = blockIdx.x;
    int t = threadIdx.x;
    __shared__ float f[FD];
    if (t < FD) f[t] = feat[row * FD + t];
    __syncthreads();
    float acc = bn[t];
#pragma unroll
    for (int k = 0; k < FD; k++) acc = fmaf(f[k], Wn[k * HD + t], acc);
    g_h[0][row * HD + t] = fmaxf(acc, 0.f);
}

// ---------------------------------------------------------------------------
// CSR build
// ---------------------------------------------------------------------------
__global__ void k_zero() {
    int i = blockIdx.x * blockDim.x + threadIdx.x;
    if (i < NN) g_cnt[i] = 0;
}

__global__ void k_count(const int* __restrict__ edges, int E) {
    int e = blockIdx.x * blockDim.x + threadIdx.x;
    if (e < E) atomicAdd(&g_cnt[edges[2 * e + 1]], 1);
}

__global__ void k_scan() {
    int t = threadIdx.x;
    int lane = t & 31;
    int w = t >> 5;
    int base = t * 8;
    int loc[8];
    int s = 0;
#pragma unroll
    for (int j = 0; j < 8; j++) { loc[j] = s; s += g_cnt[base + j]; }
    int v = s;
#pragma unroll
    for (int off = 1; off < 32; off <<= 1) {
        int u = __shfl_up_sync(0xFFFFFFFFu, v, off);
        if (lane >= off) v += u;
    }
    __shared__ int wsum[32];
    if (lane == 31) wsum[w] = v;
    __syncthreads();
    if (w == 0) {
        int x = wsum[lane];
#pragma unroll
        for (int off = 1; off < 32; off <<= 1) {
            int u = __shfl_up_sync(0xFFFFFFFFu, x, off);
            if (lane >= off) x += u;
        }
        wsum[lane] = x;
    }
    __syncthreads();
    int excl = v - s + (w ? wsum[w - 1] : 0);
#pragma unroll
    for (int j = 0; j < 8; j++) {
        int o = excl + loc[j];
        g_start[base + j] = o;
        g_fill[base + j] = o;
    }
}

__global__ void k_fill(const int* __restrict__ edges, int E) {
    int e = blockIdx.x * blockDim.x + threadIdx.x;
    if (e < E) {
        int dst = edges[2 * e + 1];
        int pos = atomicAdd(&g_fill[dst], 1);
        g_csr[pos] = edges[2 * e + 0];
    }
}

// ---------------------------------------------------------------------------
// Fused conv round; split_out: write bf16 hi/lo instead of fp32 (final round)
// ---------------------------------------------------------------------------
__global__ void k_conv(int ib, int ob, int split_out,
                       const float* __restrict__ Wc,
                       const float* __restrict__ bc) {
    const float* __restrict__ hin = g_h[ib];
    int i = blockIdx.x;
    int t = threadIdx.x;
    int s0 = g_start[i];
    int c = g_cnt[i];
    float a0 = 0.f, a1 = 0.f, a2 = 0.f, a3 = 0.f;
    int e = 0;
    for (; e + 4 <= c; e += 4) {
        int i0 = g_csr[s0 + e + 0];
        int i1 = g_csr[s0 + e + 1];
        int i2 = g_csr[s0 + e + 2];
        int i3 = g_csr[s0 + e + 3];
        a0 += hin[i0 * HD + t];
        a1 += hin[i1 * HD + t];
        a2 += hin[i2 * HD + t];
        a3 += hin[i3 * HD + t];
    }
    for (; e < c; e++) a0 += hin[g_csr[s0 + e] * HD + t];

    __shared__ float x[HD];
    x[t] = hin[i * HD + t] + ((a0 + a1) + (a2 + a3));
    __syncthreads();

    float acc = bc[t];
#pragma unroll
    for (int k = 0; k < HD; k++) acc = fmaf(x[k], Wc[k * HD + t], acc);
    acc = fmaxf(acc, 0.f);
    if (split_out) {
        __nv_bfloat16 hi = __float2bfloat16(acc);
        g_hi[i * HD + t] = hi;
        g_lo[i * HD + t] = __float2bfloat16(acc - __bfloat162float(hi));
    } else {
        g_h[ob][i * HD + t] = acc;
    }
}

// ---------------------------------------------------------------------------
// mma.sync GEMM, symmetric: upper-triangular 128x128 tiles only.
// 8 warps (2m x 4n), warp tile 64x32, K=64 bf16-split (3 terms), fp32 acc.
// Mirror tile emitted via smem transpose re-stage.
// ---------------------------------------------------------------------------
#define SM_AH 0
#define SM_AL 16384
#define SM_BH 32768
#define SM_BL 49152
// transpose buffer reuses [0, 128*132*4) after compute
#define TPITCH 132
#define SM_MASK 67584          // colmask 128 f32, rowmask 128 f32
#define SM_TOTAL 68608

__global__ void __launch_bounds__(256, 2) k_tgemm(const int* __restrict__ nodes,
                                                  float* __restrict__ out) {
    extern __shared__ char smem[];
    float* smf = (float*)smem;
    uint32_t sb = smem_u32(smem);
    int tid = threadIdx.x;
    int lane = tid & 31;
    int w = tid >> 5;
    int wm = w >> 2;
    int wn = w & 3;

    // triangular decode: by <= bx
    int bid = blockIdx.x;
    int p = (int)((sqrtf(8.f * (float)bid + 1.f) - 1.f) * 0.5f);
    while ((p + 1) * (p + 2) / 2 <= bid) p++;
    while (p * (p + 1) / 2 > bid) p--;
    int bx = p;
    int by = bid - p * (p + 1) / 2;
    int row0 = by * 128;
    int col0 = bx * 128;

    // ---- stage tiles + masks ----
    const char* pAH = (const char*)g_hi + (size_t)row0 * 128;
    const char* pAL = (const char*)g_lo + (size_t)row0 * 128;
    const char* pBH = (const char*)g_hi + (size_t)col0 * 128;
    const char* pBL = (const char*)g_lo + (size_t)col0 * 128;
#pragma unroll
    for (int q = 0; q < 4; q++) {
        int u = q * 256 + tid;
        int bo = u * 16;
        int sw = SWZ(bo);
        *(uint4*)(smem + SM_AH + sw) = *(const uint4*)(pAH + bo);
        *(uint4*)(smem + SM_AL + sw) = *(const uint4*)(pAL + bo);
        *(uint4*)(smem + SM_BH + sw) = *(const uint4*)(pBH + bo);
        *(uint4*)(smem + SM_BL + sw) = *(const uint4*)(pBL + bo);
    }
    if (tid < 128) {
        smf[SM_MASK / 4 + tid] = (nodes[col0 + tid] == 2) ? 1.f : 0.f;       // colmask
    } else {
        smf[SM_MASK / 4 + 128 + (tid - 128)] =
            (nodes[row0 + (tid - 128)] == 2) ? 1.f : 0.f;                     // rowmask
    }
    __syncthreads();

    float acc[4][4][4];
#pragma unroll
    for (int i = 0; i < 4; i++)
#pragma unroll
        for (int j = 0; j < 4; j++)
#pragma unroll
            for (int cc = 0; cc < 4; cc++) acc[i][j][cc] = 0.f;

    int a_row = (lane & 7) + 8 * ((lane >> 3) & 1);
    int a_kh = (lane >> 4);
    int l16 = lane & 15;
    int b_col = l16 & 7;
    int b_kh = l16 >> 3;

#pragma unroll
    for (int ks = 0; ks < 4; ks++) {
        int k0 = ks * 16;
        uint32_t bH[4][2], bL[4][2];
#pragma unroll
        for (int nt = 0; nt < 4; nt++) {
            int cgl = wn * 32 + nt * 8 + b_col;
            int bo = cgl * 128 + (k0 + 8 * b_kh) * 2;
            int sw = SWZ(bo);
            ldm_x2(bH[nt], sb + SM_BH + sw);
            ldm_x2(bL[nt], sb + SM_BL + sw);
        }
#pragma unroll
        for (int mt = 0; mt < 4; mt++) {
            uint32_t aH[4], aL[4];
            int r = wm * 64 + mt * 16 + a_row;
            int bo = r * 128 + (k0 + 8 * a_kh) * 2;
            int sw = SWZ(bo);
            ldm_x4(aH, sb + SM_AH + sw);
            ldm_x4(aL, sb + SM_AL + sw);
#pragma unroll
            for (int nt = 0; nt < 4; nt++) {
                mma_bf16(acc[mt][nt], aH, bH[nt]);
                mma_bf16(acc[mt][nt], aH, bL[nt]);
                mma_bf16(acc[mt][nt], aL, bH[nt]);
            }
        }
    }

    // ---- masks for direct stores ----
    float mr[4][2];
#pragma unroll
    for (int mt = 0; mt < 4; mt++) {
        int r = row0 + wm * 64 + mt * 16 + (lane >> 2);
        mr[mt][0] = (nodes[r] == 2) ? 1.f : 0.f;
        mr[mt][1] = (nodes[r + 8] == 2) ? 1.f : 0.f;
    }
    float mc[4][2];
#pragma unroll
    for (int nt = 0; nt < 4; nt++) {
        int c = col0 + wn * 32 + nt * 8 + 2 * (lane & 3);
        mc[nt][0] = (nodes[c] == 2) ? 1.f : 0.f;
        mc[nt][1] = (nodes[c + 1] == 2) ? 1.f : 0.f;
    }

    float* out_dep = out;
    float* out_sim = out + (size_t)NN * NN;

    // ---- direct tile stores ----
#pragma unroll
    for (int mt = 0; mt < 4; mt++) {
        int r0 = row0 + wm * 64 + mt * 16 + (lane >> 2);
        int r1 = r0 + 8;
#pragma unroll
        for (int nt = 0; nt < 4; nt++) {
            int c = col0 + wn * 32 + nt * 8 + 2 * (lane & 3);
            const float* a4 = acc[mt][nt];
            *(float2*)&out_sim[(size_t)r0 * NN + c] = make_float2(a4[0], a4[1]);
            *(float2*)&out_sim[(size_t)r1 * NN + c] = make_float2(a4[2], a4[3]);
            *(float2*)&out_dep[(size_t)r0 * NN + c] =
                make_float2(a4[0] * mr[mt][0] * mc[nt][0],
                            a4[1] * mr[mt][0] * mc[nt][1]);
            *(float2*)&out_dep[(size_t)r1 * NN + c] =
                make_float2(a4[2] * mr[mt][1] * mc[nt][0],
                            a4[3] * mr[mt][1] * mc[nt][1]);
        }
    }

    // ---- mirror tile via smem transpose (skip diagonal) ----
    if (bx == by) return;
    __syncthreads();   // everyone done reading staged A/B
#pragma unroll
    for (int mt = 0; mt < 4; mt++) {
        int r0 = wm * 64 + mt * 16 + (lane >> 2);
        int r1 = r0 + 8;
#pragma unroll
        for (int nt = 0; nt < 4; nt++) {
            int c0 = wn * 32 + nt * 8 + 2 * (lane & 3);
            const float* a4 = acc[mt][nt];
            smf[(c0 + 0) * TPITCH + r0] = a4[0];
            smf[(c0 + 1) * TPITCH + r0] = a4[1];
            smf[(c0 + 0) * TPITCH + r1] = a4[2];
            smf[(c0 + 1) * TPITCH + r1] = a4[3];
        }
    }
    __syncthreads();

    int rr = tid >> 1;            // mirror-tile row = original col
    int hh = tid & 1;             // half: 64 floats
    float mrow = smf[SM_MASK / 4 + rr];             // colmask[rr]
    size_t base = (size_t)(col0 + rr) * NN + row0 + hh * 64;
    const float* trow = &smf[rr * TPITCH + hh * 64];
    const float* cm = &smf[SM_MASK / 4 + 128 + hh * 64];   // rowmask slice
#pragma unroll
    for (int j = 0; j < 16; j++) {
        float4 v = *(const float4*)(trow + j * 4);
        *(float4*)&out_sim[base + j * 4] = v;
        float4 m = *(const float4*)(cm + j * 4);
        *(float4*)&out_dep[base + j * 4] =
            make_float4(v.x * mrow * m.x, v.y * mrow * m.y,
                        v.z * mrow * m.z, v.w * mrow * m.w);
    }
}

// ---------------------------------------------------------------------------
extern "C" void kernel_launch(void* const* d_in, const int* in_sizes, int n_in,
                              void* d_out, int out_size) {
    const float* feat = (const float*)d_in[0];
    const float* Wn   = (const float*)d_in[1];
    const float* bn   = (const float*)d_in[2];
    const float* Wc   = (const float*)d_in[3];
    const float* bc   = (const float*)d_in[4];
    const int* nodes  = (const int*)d_in[5];
    const int* edges  = (const int*)d_in[6];
    int E = in_sizes[6] / 2;
    float* out = (float*)d_out;

    k_node<<<NN, 64>>>(feat, Wn, bn);

    k_zero<<<(NN + 255) / 256, 256>>>();
    k_count<<<(E + 255) / 256, 256>>>(edges, E);
    k_scan<<<1, 1024>>>();
    k_fill<<<(E + 255) / 256, 256>>>(edges, E);

    k_conv<<<NN, 64>>>(0, 1, 0, Wc, bc);
    k_conv<<<NN, 64>>>(1, 0, 1, Wc, bc);   // final round writes bf16 hi/lo

    cudaFuncSetAttribute(k_tgemm, cudaFuncAttributeMaxDynamicSharedMemorySize,
                         SM_TOTAL);
    int ntiles = (NN / 128) * (NN / 128 + 1) / 2;  // 2080
    k_tgemm<<<ntiles, 256, SM_TOTAL>>>(nodes, out);

    (void)n_in; (void)out_size;
}

// round 7
// speedup vs baseline: 1.2541x; 1.2541x over previous
#include <cuda_runtime.h>
#include <cuda_bf16.h>
#include <cstdint>

#define NN 8192
#define FD 10
#define HD 64
#define EMX 524288

__device__ float g_h[2][NN * HD];
__device__ __nv_bfloat16 g_hi[NN * HD];
__device__ __nv_bfloat16 g_lo[NN * HD];
__device__ int g_cnt[NN];
__device__ int g_start[NN];
__device__ int g_fill[NN];
__device__ int g_csr[EMX];

// ---------------------------------------------------------------------------
// helpers
// ---------------------------------------------------------------------------
__device__ __forceinline__ uint32_t smem_u32(const void* p) {
    uint32_t a;
    asm("{ .reg .u64 t; cvta.to.shared.u64 t, %1; cvt.u32.u64 %0, t; }"
        : "=r"(a) : "l"(p));
    return a;
}

__device__ __forceinline__ void ldm_x4(uint32_t* r, uint32_t addr) {
    asm volatile("ldmatrix.sync.aligned.m8n8.x4.shared.b16 {%0,%1,%2,%3}, [%4];"
                 : "=r"(r[0]), "=r"(r[1]), "=r"(r[2]), "=r"(r[3]) : "r"(addr));
}
__device__ __forceinline__ void ldm_x2(uint32_t* r, uint32_t addr) {
    asm volatile("ldmatrix.sync.aligned.m8n8.x2.shared.b16 {%0,%1}, [%2];"
                 : "=r"(r[0]), "=r"(r[1]) : "r"(addr));
}
__device__ __forceinline__ void mma_bf16(float* c, const uint32_t* a,
                                         const uint32_t* b) {
    asm volatile(
        "mma.sync.aligned.m16n8k16.row.col.f32.bf16.bf16.f32 "
        "{%0,%1,%2,%3}, {%4,%5,%6,%7}, {%8,%9}, {%0,%1,%2,%3};"
        : "+f"(c[0]), "+f"(c[1]), "+f"(c[2]), "+f"(c[3])
        : "r"(a[0]), "r"(a[1]), "r"(a[2]), "r"(a[3]), "r"(b[0]), "r"(b[1]));
}

#define SWZ(bo) ((bo) ^ (((bo) >> 3) & 0x70))

// ---------------------------------------------------------------------------
// h0 = relu(features @ W_node + b_node)
// ---------------------------------------------------------------------------
__global__ void k_node(const float* __restrict__ feat,
                       const float* __restrict__ Wn,
                       const float* __restrict__ bn) {
    int row = blockIdx.x;
    int t = threadIdx.x;
    __shared__ float f[FD];
    if (t < FD) f[t] = feat[row * FD + t];
    __syncthreads();
    float acc = bn[t];
#pragma unroll
    for (int k = 0; k < FD; k++) acc = fmaf(f[k], Wn[k * HD + t], acc);
    g_h[0][row * HD + t] = fmaxf(acc, 0.f);
}

// ---------------------------------------------------------------------------
// CSR build
// ---------------------------------------------------------------------------
__global__ void k_zero() {
    int i = blockIdx.x * blockDim.x + threadIdx.x;
    if (i < NN) g_cnt[i] = 0;
}

__global__ void k_count(const int* __restrict__ edges, int E) {
    int e = blockIdx.x * blockDim.x + threadIdx.x;
    if (e < E) atomicAdd(&g_cnt[edges[2 * e + 1]], 1);
}

__global__ void k_scan() {
    int t = threadIdx.x;
    int lane = t & 31;
    int w = t >> 5;
    int base = t * 8;
    int loc[8];
    int s = 0;
#pragma unroll
    for (int j = 0; j < 8; j++) { loc[j] = s; s += g_cnt[base + j]; }
    int v = s;
#pragma unroll
    for (int off = 1; off < 32; off <<= 1) {
        int u = __shfl_up_sync(0xFFFFFFFFu, v, off);
        if (lane >= off) v += u;
    }
    __shared__ int wsum[32];
    if (lane == 31) wsum[w] = v;
    __syncthreads();
    if (w == 0) {
        int x = wsum[lane];
#pragma unroll
        for (int off = 1; off < 32; off <<= 1) {
            int u = __shfl_up_sync(0xFFFFFFFFu, x, off);
            if (lane >= off) x += u;
        }
        wsum[lane] = x;
    }
    __syncthreads();
    int excl = v - s + (w ? wsum[w - 1] : 0);
#pragma unroll
    for (int j = 0; j < 8; j++) {
        int o = excl + loc[j];
        g_start[base + j] = o;
        g_fill[base + j] = o;
    }
}

__global__ void k_fill(const int* __restrict__ edges, int E) {
    int e = blockIdx.x * blockDim.x + threadIdx.x;
    if (e < E) {
        int dst = edges[2 * e + 1];
        int pos = atomicAdd(&g_fill[dst], 1);
        g_csr[pos] = edges[2 * e + 0];
    }
}

// ---------------------------------------------------------------------------
// Fused conv round; split_out: final round writes bf16 hi/lo
// ---------------------------------------------------------------------------
__global__ void k_conv(int ib, int ob, int split_out,
                       const float* __restrict__ Wc,
                       const float* __restrict__ bc) {
    const float* __restrict__ hin = g_h[ib];
    int i = blockIdx.x;
    int t = threadIdx.x;
    int s0 = g_start[i];
    int c = g_cnt[i];
    float a0 = 0.f, a1 = 0.f, a2 = 0.f, a3 = 0.f;
    int e = 0;
    for (; e + 4 <= c; e += 4) {
        int i0 = g_csr[s0 + e + 0];
        int i1 = g_csr[s0 + e + 1];
        int i2 = g_csr[s0 + e + 2];
        int i3 = g_csr[s0 + e + 3];
        a0 += hin[i0 * HD + t];
        a1 += hin[i1 * HD + t];
        a2 += hin[i2 * HD + t];
        a3 += hin[i3 * HD + t];
    }
    for (; e < c; e++) a0 += hin[g_csr[s0 + e] * HD + t];

    __shared__ float x[HD];
    x[t] = hin[i * HD + t] + ((a0 + a1) + (a2 + a3));
    __syncthreads();

    float acc = bc[t];
#pragma unroll
    for (int k = 0; k < HD; k++) acc = fmaf(x[k], Wc[k * HD + t], acc);
    acc = fmaxf(acc, 0.f);
    if (split_out) {
        __nv_bfloat16 hi = __float2bfloat16(acc);
        g_hi[i * HD + t] = hi;
        g_lo[i * HD + t] = __float2bfloat16(acc - __bfloat162float(hi));
    } else {
        g_h[ob][i * HD + t] = acc;
    }
}

// ---------------------------------------------------------------------------
// mma.sync GEMM: CTA tile 128(m) x 64(n), full grid, K=64 bf16-split (3 terms).
// 8 warps (2m x 4n), warp tile 64x16 -> acc[4][2][4] = 32 floats/thread.
// ~90 regs -> 2 CTAs/SM without spill.
// ---------------------------------------------------------------------------
#define SM_AH 0
#define SM_AL 16384
#define SM_BH 32768
#define SM_BL 40960
#define SM_TOTAL 49152

__global__ void __launch_bounds__(256, 2) k_tgemm(const int* __restrict__ nodes,
                                                  float* __restrict__ out) {
    extern __shared__ char smem[];
    uint32_t sb = smem_u32(smem);
    int tid = threadIdx.x;
    int lane = tid & 31;
    int w = tid >> 5;
    int wm = w >> 2;   // 0..1  (64-row half)
    int wn = w & 3;    // 0..3  (16-col slice)

    int row0 = blockIdx.y * 128;
    int col0 = blockIdx.x * 64;

    // ---- stage tiles: A 128 rows, B 64 rows (each row 128B, SW128) ----
    const char* pAH = (const char*)g_hi + (size_t)row0 * 128;
    const char* pAL = (const char*)g_lo + (size_t)row0 * 128;
    const char* pBH = (const char*)g_hi + (size_t)col0 * 128;
    const char* pBL = (const char*)g_lo + (size_t)col0 * 128;
#pragma unroll
    for (int q = 0; q < 4; q++) {
        int u = q * 256 + tid;   // 0..1023
        int bo = u * 16;
        int sw = SWZ(bo);
        *(uint4*)(smem + SM_AH + sw) = *(const uint4*)(pAH + bo);
        *(uint4*)(smem + SM_AL + sw) = *(const uint4*)(pAL + bo);
    }
#pragma unroll
    for (int q = 0; q < 2; q++) {
        int u = q * 256 + tid;   // 0..511
        int bo = u * 16;
        int sw = SWZ(bo);
        *(uint4*)(smem + SM_BH + sw) = *(const uint4*)(pBH + bo);
        *(uint4*)(smem + SM_BL + sw) = *(const uint4*)(pBL + bo);
    }
    __syncthreads();

    float acc[4][2][4];
#pragma unroll
    for (int i = 0; i < 4; i++)
#pragma unroll
        for (int j = 0; j < 2; j++)
#pragma unroll
            for (int cc = 0; cc < 4; cc++) acc[i][j][cc] = 0.f;

    int a_row = (lane & 7) + 8 * ((lane >> 3) & 1);
    int a_kh = (lane >> 4);
    int l16 = lane & 15;
    int b_col = l16 & 7;
    int b_kh = l16 >> 3;

#pragma unroll
    for (int ks = 0; ks < 4; ks++) {
        int k0 = ks * 16;
        uint32_t bH[2][2], bL[2][2];
#pragma unroll
        for (int nt = 0; nt < 2; nt++) {
            int cgl = wn * 16 + nt * 8 + b_col;
            int bo = cgl * 128 + (k0 + 8 * b_kh) * 2;
            int sw = SWZ(bo);
            ldm_x2(bH[nt], sb + SM_BH + sw);
            ldm_x2(bL[nt], sb + SM_BL + sw);
        }
#pragma unroll
        for (int mt = 0; mt < 4; mt++) {
            uint32_t aH[4], aL[4];
            int r = wm * 64 + mt * 16 + a_row;
            int bo = r * 128 + (k0 + 8 * a_kh) * 2;
            int sw = SWZ(bo);
            ldm_x4(aH, sb + SM_AH + sw);
            ldm_x4(aL, sb + SM_AL + sw);
#pragma unroll
            for (int nt = 0; nt < 2; nt++) {
                mma_bf16(acc[mt][nt], aH, bH[nt]);
                mma_bf16(acc[mt][nt], aH, bL[nt]);
                mma_bf16(acc[mt][nt], aL, bH[nt]);
            }
        }
    }

    // ---- masks ----
    float mr[4][2];
#pragma unroll
    for (int mt = 0; mt < 4; mt++) {
        int r = row0 + wm * 64 + mt * 16 + (lane >> 2);
        mr[mt][0] = (nodes[r] == 2) ? 1.f : 0.f;
        mr[mt][1] = (nodes[r + 8] == 2) ? 1.f : 0.f;
    }
    float mc[2][2];
#pragma unroll
    for (int nt = 0; nt < 2; nt++) {
        int c = col0 + wn * 16 + nt * 8 + 2 * (lane & 3);
        mc[nt][0] = (nodes[c] == 2) ? 1.f : 0.f;
        mc[nt][1] = (nodes[c + 1] == 2) ? 1.f : 0.f;
    }

    float* out_dep = out;
    float* out_sim = out + (size_t)NN * NN;

#pragma unroll
    for (int mt = 0; mt < 4; mt++) {
        int r0 = row0 + wm * 64 + mt * 16 + (lane >> 2);
        int r1 = r0 + 8;
#pragma unroll
        for (int nt = 0; nt < 2; nt++) {
            int c = col0 + wn * 16 + nt * 8 + 2 * (lane & 3);
            const float* a4 = acc[mt][nt];
            *(float2*)&out_sim[(size_t)r0 * NN + c] = make_float2(a4[0], a4[1]);
            *(float2*)&out_sim[(size_t)r1 * NN + c] = make_float2(a4[2], a4[3]);
            *(float2*)&out_dep[(size_t)r0 * NN + c] =
                make_float2(a4[0] * mr[mt][0] * mc[nt][0],
                            a4[1] * mr[mt][0] * mc[nt][1]);
            *(float2*)&out_dep[(size_t)r1 * NN + c] =
                make_float2(a4[2] * mr[mt][1] * mc[nt][0],
                            a4[3] * mr[mt][1] * mc[nt][1]);
        }
    }
}

// ---------------------------------------------------------------------------
extern "C" void kernel_launch(void* const* d_in, const int* in_sizes, int n_in,
                              void* d_out, int out_size) {
    const float* feat = (const float*)d_in[0];
    const float* Wn   = (const float*)d_in[1];
    const float* bn   = (const float*)d_in[2];
    const float* Wc   = (const float*)d_in[3];
    const float* bc   = (const float*)d_in[4];
    const int* nodes  = (const int*)d_in[5];
    const int* edges  = (const int*)d_in[6];
    int E = in_sizes[6] / 2;
    float* out = (float*)d_out;

    k_node<<<NN, 64>>>(feat, Wn, bn);

    k_zero<<<(NN + 255) / 256, 256>>>();
    k_count<<<(E + 255) / 256, 256>>>(edges, E);
    k_scan<<<1, 1024>>>();
    k_fill<<<(E + 255) / 256, 256>>>(edges, E);

    k_conv<<<NN, 64>>>(0, 1, 0, Wc, bc);
    k_conv<<<NN, 64>>>(1, 0, 1, Wc, bc);   // final round writes bf16 hi/lo

    cudaFuncSetAttribute(k_tgemm, cudaFuncAttributeMaxDynamicSharedMemorySize,
                         SM_TOTAL);
    dim3 grid(NN / 64, NN / 128);   // (128, 64)
    k_tgemm<<<grid, 256, SM_TOTAL>>>(nodes, out);

    (void)n_in; (void)out_size;
}